// round 2
// baseline (speedup 1.0000x reference)
#include <cuda_runtime.h>
#include <math.h>
#include <math_constants.h>

// Problem shapes (fixed by the dataset)
#define B_ 64
#define C_ 5
#define H_ 50
#define S_ 32
#define E_ 768
#define D_ 768
#define K_ 5
#define CROWS (B_*C_)            // 320 candidate rows
#define HROWS (B_*H_)            // 3200 history rows
#define ROWS (CROWS + HROWS)     // 3520 total projected rows
#define SEL (CROWS*K_)           // 1600 gather selections
#define SE (S_*E_)               // 24576 floats per selection

// ---------------- scratch (static device globals; no allocation) -----------
__device__ float  g_P[ROWS * D_];       // projected rows (pre-normalization)
__device__ double g_inv[ROWS];          // 1/norm per row
__device__ double g_attn[CROWS * H_];   // masked attention scores
__device__ int    g_idx[SEL];           // top-K indices per (b,c)

// ---------------- 1) projection GEMM: P[r,n] = X[r,:]·W[n,:] + bias[n] -----
#define BM 64
#define BN 64
#define BK 16

__global__ void proj_gemm(const float* __restrict__ cdd,
                          const float* __restrict__ his,
                          const float* __restrict__ W,
                          const float* __restrict__ bias) {
    __shared__ float As[BK][BM];   // k-major tiles for conflict-free LDS.128
    __shared__ float Bs[BK][BN];

    const int m0 = blockIdx.x * BM;
    const int n0 = blockIdx.y * BN;
    const int t  = threadIdx.x;          // 256 threads
    const int tx = t & 15, ty = t >> 4;  // 16x16 thread grid, 4x4 micro-tile

    // loader mapping: each thread loads one float4 along k for one row
    const int lrow = t >> 2;             // 0..63
    const int kq   = (t & 3) << 2;       // 0,4,8,12
    const int gr   = m0 + lrow;
    const float* xsrc = (gr < CROWS) ? (cdd + (size_t)gr * D_)
                                     : (his + (size_t)(gr - CROWS) * D_);
    const float* wsrc = W + (size_t)(n0 + lrow) * D_;

    float acc[4][4] = {};

    for (int k0 = 0; k0 < D_; k0 += BK) {
        float4 a = *(const float4*)(xsrc + k0 + kq);
        float4 b = *(const float4*)(wsrc + k0 + kq);
        As[kq+0][lrow] = a.x; As[kq+1][lrow] = a.y;
        As[kq+2][lrow] = a.z; As[kq+3][lrow] = a.w;
        Bs[kq+0][lrow] = b.x; Bs[kq+1][lrow] = b.y;
        Bs[kq+2][lrow] = b.z; Bs[kq+3][lrow] = b.w;
        __syncthreads();

        #pragma unroll
        for (int kk = 0; kk < BK; kk++) {
            float4 av = *(const float4*)&As[kk][ty << 2];
            float4 bv = *(const float4*)&Bs[kk][tx << 2];
            float aa[4] = {av.x, av.y, av.z, av.w};
            float bb[4] = {bv.x, bv.y, bv.z, bv.w};
            #pragma unroll
            for (int i = 0; i < 4; i++)
                #pragma unroll
                for (int j = 0; j < 4; j++)
                    acc[i][j] = fmaf(aa[i], bb[j], acc[i][j]);
        }
        __syncthreads();
    }

    #pragma unroll
    for (int i = 0; i < 4; i++) {
        const int r = m0 + (ty << 2) + i;
        #pragma unroll
        for (int j = 0; j < 4; j++) {
            const int n = n0 + (tx << 2) + j;
            g_P[(size_t)r * D_ + n] = acc[i][j] + bias[n];
        }
    }
}

// ---------------- 2) row norms (fp64 accumulate) ---------------------------
__global__ void rownorm_kernel() {
    const int r = blockIdx.x;
    const float* p = g_P + (size_t)r * D_;
    double s = 0.0;
    for (int k = threadIdx.x; k < D_; k += 256) {
        double v = (double)p[k];
        s += v * v;
    }
    #pragma unroll
    for (int o = 16; o; o >>= 1) s += __shfl_down_sync(0xffffffffu, s, o);
    __shared__ double red[8];
    const int w = threadIdx.x >> 5, l = threadIdx.x & 31;
    if (l == 0) red[w] = s;
    __syncthreads();
    if (threadIdx.x == 0) {
        double tot = 0.0;
        #pragma unroll
        for (int i = 0; i < 8; i++) tot += red[i];
        double n = sqrt(tot);
        if (n < 1e-12) n = 1e-12;
        g_inv[r] = 1.0 / n;
    }
}

// ---------------- 3) attention scores + masking (fp64 accumulate) ----------
__global__ void attn_kernel(const int* __restrict__ his_mask) {
    const int bc = blockIdx.x;      // 0..319  (= b*C + c = candidate row)
    const int b  = bc / C_;
    const int w  = threadIdx.x >> 5, l = threadIdx.x & 31;
    const float* pc = g_P + (size_t)bc * D_;
    for (int h = w; h < H_; h += 8) {
        const int hrow = CROWS + b * H_ + h;
        const float* ph = g_P + (size_t)hrow * D_;
        double s = 0.0;
        for (int k = l; k < D_; k += 32)
            s += (double)pc[k] * (double)ph[k];
        #pragma unroll
        for (int o = 16; o; o >>= 1) s += __shfl_down_sync(0xffffffffu, s, o);
        if (l == 0) {
            const bool valid = (his_mask[b * H_ + h] != 0) || (h < K_);
            g_attn[bc * H_ + h] = valid ? s * g_inv[bc] * g_inv[hrow]
                                        : -CUDART_INF;
        }
    }
}

// ---------------- 4) top-K (one warp per (b,c); stable tie = lowest idx) ---
__global__ void topk_kernel() {
    const int gw = (blockIdx.x * blockDim.x + threadIdx.x) >> 5;
    const int l  = threadIdx.x & 31;
    if (gw >= CROWS) return;
    const double* a = g_attn + (size_t)gw * H_;

    double v0 = (l      < H_) ? a[l]      : -CUDART_INF;
    double v1 = (l + 32 < H_) ? a[l + 32] : -CUDART_INF;
    bool used0 = false, used1 = false;

    for (int k = 0; k < K_; k++) {
        double bv = -CUDART_INF;
        int    bi = 1 << 30;
        if (!used1)                           { bv = v1; bi = l + 32; }
        if (!used0 && (used1 || v0 >= v1))    { bv = v0; bi = l; }
        #pragma unroll
        for (int o = 16; o; o >>= 1) {
            double ov = __shfl_down_sync(0xffffffffu, bv, o);
            int    oi = __shfl_down_sync(0xffffffffu, bi, o);
            if (ov > bv || (ov == bv && oi < bi)) { bv = ov; bi = oi; }
        }
        bi = __shfl_sync(0xffffffffu, bi, 0);
        if (l == 0) g_idx[gw * K_ + k] = bi;
        if (bi == l)      used0 = true;
        if (bi == l + 32) used1 = true;
    }
}

// ---------------- 5) embedding gather (the bandwidth-bound copy) -----------
// grid = SEL * 8 blocks; each block copies 1/8 of one 96KB selection via float4
__global__ void gather_emb(const float* __restrict__ emb, float* __restrict__ out) {
    const int sel  = blockIdx.x >> 3;
    const int part = blockIdx.x & 7;
    const int b    = sel / (C_ * K_);
    const int idx  = g_idx[sel];
    const float4* src = (const float4*)(emb + ((size_t)b * H_ + idx) * SE);
    float4*       dst = (float4*)(out + (size_t)sel * SE);
    const int base = part * 768;                 // SE/4 = 6144 ; /8 = 768 float4
    #pragma unroll
    for (int i = 0; i < 3; i++) {
        const int o = base + threadIdx.x + i * 256;
        dst[o] = src[o];
    }
}

// ---------------- 6) attention-mask gather (cast int -> float) -------------
__global__ void gather_mask(const int* __restrict__ am, float* __restrict__ outm) {
    const int i = blockIdx.x * blockDim.x + threadIdx.x;
    if (i >= SEL * S_) return;                   // 51200
    const int sel = i >> 5, s = i & 31;
    const int b   = sel / (C_ * K_);
    const int idx = g_idx[sel];
    outm[i] = (float)am[((size_t)b * H_ + idx) * S_ + s];
}

// ---------------------------------------------------------------------------
extern "C" void kernel_launch(void* const* d_in, const int* in_sizes, int n_in,
                              void* d_out, int out_size) {
    const float* cdd  = (const float*)d_in[0];   // [B,C,D]
    const float* his  = (const float*)d_in[1];   // [B,H,D]
    const float* emb  = (const float*)d_in[2];   // [B,H,S,E]
    const int*   am   = (const int*)  d_in[3];   // [B,H,S]
    const int*   hm   = (const int*)  d_in[4];   // [B,H,1]
    const float* W    = (const float*)d_in[5];   // [D,D]
    const float* bias = (const float*)d_in[6];   // [D]
    float* out = (float*)d_out;                  // [B,C,K,S,E] ++ [B,C,K,S]

    dim3 gg(ROWS / BM, D_ / BN);                 // 55 x 12
    proj_gemm<<<gg, 256>>>(cdd, his, W, bias);
    rownorm_kernel<<<ROWS, 256>>>();
    attn_kernel<<<CROWS, 256>>>(hm);
    topk_kernel<<<(CROWS * 32 + 255) / 256, 256>>>();
    gather_emb<<<SEL * 8, 256>>>(emb, out);
    gather_mask<<<(SEL * S_ + 255) / 256, 256>>>(am, out + (size_t)SEL * SE);
}

// round 4
// speedup vs baseline: 1.1538x; 1.1538x over previous
#include <cuda_runtime.h>
#include <cuda_bf16.h>
#include <math.h>
#include <math_constants.h>
#include <cstdint>

// Problem shapes (fixed by the dataset)
#define B_ 64
#define C_ 5
#define H_ 50
#define S_ 32
#define E_ 768
#define D_ 768
#define K_ 5
#define CROWS (B_*C_)            // 320 candidate rows
#define HROWS (B_*H_)            // 3200 history rows
#define ROWS (CROWS + HROWS)     // 3520 total projected rows
#define ROWSP 3584               // padded to multiple of 128
#define SEL (CROWS*K_)           // 1600 gather selections
#define SE (S_*E_)               // 24576 floats per selection

// ---------------- scratch (static device globals; no allocation) -----------
__device__ __nv_bfloat16 g_Xs[3][(size_t)ROWSP * D_];  // X split limbs (padded rows zeroed)
__device__ __nv_bfloat16 g_Ws[3][(size_t)D_ * D_];     // W split limbs
__device__ float  g_P[(size_t)ROWSP * D_];             // projected rows (padded)
__device__ double g_inv[ROWS];                         // 1/norm per row
__device__ int    g_idx[SEL];                          // top-K indices per (b,c)

// ======================= small helpers =====================================
__device__ __forceinline__ uint32_t smem_u32(const void* p) {
    uint32_t a;
    asm("{ .reg .u64 t; cvta.to.shared.u64 t, %1; cvt.u32.u64 %0, t; }" : "=r"(a) : "l"(p));
    return a;
}
__device__ __forceinline__ void cp_async16(uint32_t dst, const void* src) {
    asm volatile("cp.async.cg.shared.global [%0], [%1], 16;"
                 :: "r"(dst), "l"(__cvta_generic_to_global(src)));
}
#define CP_COMMIT() asm volatile("cp.async.commit_group;" ::: "memory")
#define CP_WAIT(n)  asm volatile("cp.async.wait_group %0;" :: "n"(n) : "memory")

__device__ __forceinline__ void ldsm4(uint32_t addr, uint32_t& r0, uint32_t& r1,
                                      uint32_t& r2, uint32_t& r3) {
    asm volatile("ldmatrix.sync.aligned.m8n8.x4.shared.b16 {%0,%1,%2,%3}, [%4];"
                 : "=r"(r0), "=r"(r1), "=r"(r2), "=r"(r3) : "r"(addr));
}
__device__ __forceinline__ void mma16816(float* c, const uint32_t* a,
                                         uint32_t b0, uint32_t b1) {
    asm volatile("mma.sync.aligned.m16n8k16.row.col.f32.bf16.bf16.f32 "
                 "{%0,%1,%2,%3}, {%4,%5,%6,%7}, {%8,%9}, {%0,%1,%2,%3};"
                 : "+f"(c[0]), "+f"(c[1]), "+f"(c[2]), "+f"(c[3])
                 : "r"(a[0]), "r"(a[1]), "r"(a[2]), "r"(a[3]), "r"(b0), "r"(b1));
}

// ================== 0) split fp32 -> 3 bf16 limbs ==========================
__global__ void split_kernel(const float* __restrict__ cdd,
                             const float* __restrict__ his,
                             const float* __restrict__ W) {
    const size_t NX = (size_t)ROWSP * D_;
    const size_t NW = (size_t)D_ * D_;
    size_t i = (size_t)blockIdx.x * blockDim.x + threadIdx.x;
    if (i < NX) {
        size_t row = i / D_, col = i % D_;
        float v = 0.f;
        if (row < CROWS)      v = cdd[row * D_ + col];
        else if (row < ROWS)  v = his[(row - CROWS) * D_ + col];
        __nv_bfloat16 b1 = __float2bfloat16(v);
        float r1 = v - __bfloat162float(b1);
        __nv_bfloat16 b2 = __float2bfloat16(r1);
        float r2 = r1 - __bfloat162float(b2);
        __nv_bfloat16 b3 = __float2bfloat16(r2);
        g_Xs[0][i] = b1; g_Xs[1][i] = b2; g_Xs[2][i] = b3;
    } else if (i < NX + NW) {
        size_t j = i - NX;
        float v = W[j];
        __nv_bfloat16 b1 = __float2bfloat16(v);
        float r1 = v - __bfloat162float(b1);
        __nv_bfloat16 b2 = __float2bfloat16(r1);
        float r2 = r1 - __bfloat162float(b2);
        __nv_bfloat16 b3 = __float2bfloat16(r2);
        g_Ws[0][j] = b1; g_Ws[1][j] = b2; g_Ws[2][j] = b3;
    }
}

// ================== 1) mma.sync bf16x3 GEMM: P = X·Wᵀ + b ==================
// CTA tile 128x128, K-chunk 32, double-buffered cp.async, 6 limb products.
// 8 warps (2x4): warp tile 64x32. Padded smem stride 40 bf16 (80B).
#define NPROD 6
#define KC 32
#define NKT (D_ / KC)                    // 24
#define NIT (NPROD * NKT)                // 144
#define SSTRIDE 40                       // bf16 elements per smem row

__constant__ int c_pa[NPROD] = {0, 0, 1, 0, 2, 1};
__constant__ int c_pb[NPROD] = {0, 1, 0, 2, 0, 1};

__global__ void __launch_bounds__(256, 2)
gemm_mma(const float* __restrict__ bias) {
    __shared__ __nv_bfloat16 sA[2][128 * SSTRIDE];
    __shared__ __nv_bfloat16 sB[2][128 * SSTRIDE];

    const int tid  = threadIdx.x;
    const int wid  = tid >> 5, lane = tid & 31;
    const int m0   = blockIdx.x * 128;
    const int n0   = blockIdx.y * 128;
    const int wm   = (wid >> 2) * 64;     // warp m offset within tile
    const int wn   = (wid & 3) * 32;      // warp n offset within tile

    const uint32_t sAb[2] = { smem_u32(&sA[0][0]), smem_u32(&sA[1][0]) };
    const uint32_t sBb[2] = { smem_u32(&sB[0][0]), smem_u32(&sB[1][0]) };

    // loader mapping: 4 chunks of 16B per thread
    const int jrow[4] = { (tid) >> 2, (tid + 256) >> 2, (tid) >> 2, (tid + 256) >> 2 };
    const int jq  = tid & 3;

    float acc[4][4][4];
    #pragma unroll
    for (int i = 0; i < 4; i++)
        #pragma unroll
        for (int j = 0; j < 4; j++)
            #pragma unroll
            for (int v = 0; v < 4; v++) acc[i][j][v] = 0.f;

    auto load_tile = [&](int it, int buf) {
        const int p  = it / NKT;
        const int kb = (it % NKT) * KC;
        const __nv_bfloat16* Asrc = g_Xs[c_pa[p]];
        const __nv_bfloat16* Bsrc = g_Ws[c_pb[p]];
        #pragma unroll
        for (int h = 0; h < 2; h++) {     // two row groups for A, two for B
            const int row = jrow[h];      // 0..127
            cp_async16(sAb[buf] + (uint32_t)(row * SSTRIDE + jq * 8) * 2,
                       Asrc + (size_t)(m0 + row) * D_ + kb + jq * 8);
            cp_async16(sBb[buf] + (uint32_t)(row * SSTRIDE + jq * 8) * 2,
                       Bsrc + (size_t)(n0 + row) * D_ + kb + jq * 8);
        }
        CP_COMMIT();
    };

    load_tile(0, 0);

    const int lrow = lane & 15;                 // ldmatrix row within 16
    const int lcol = (lane >> 4) << 3;          // 0 or 8

    for (int it = 0; it < NIT; it++) {
        const int buf = it & 1;
        if (it + 1 < NIT) { load_tile(it + 1, buf ^ 1); CP_WAIT(1); }
        else              { CP_WAIT(0); }
        __syncthreads();

        #pragma unroll
        for (int kh = 0; kh < 2; kh++) {        // k16 steps
            const int kb = kh * 16;
            uint32_t a[4][4];
            #pragma unroll
            for (int mf = 0; mf < 4; mf++) {
                uint32_t addr = sAb[buf] +
                    (uint32_t)((wm + mf * 16 + lrow) * SSTRIDE + kb + lcol) * 2;
                ldsm4(addr, a[mf][0], a[mf][1], a[mf][2], a[mf][3]);
            }
            uint32_t bfr[2][4];
            #pragma unroll
            for (int nb = 0; nb < 2; nb++) {
                uint32_t addr = sBb[buf] +
                    (uint32_t)((wn + nb * 16 + lrow) * SSTRIDE + kb + lcol) * 2;
                ldsm4(addr, bfr[nb][0], bfr[nb][1], bfr[nb][2], bfr[nb][3]);
            }
            #pragma unroll
            for (int mf = 0; mf < 4; mf++)
                #pragma unroll
                for (int oct = 0; oct < 4; oct++) {
                    const int nb = oct >> 1, par = oct & 1;
                    mma16816(acc[mf][oct], a[mf], bfr[nb][par], bfr[nb][par + 2]);
                }
        }
        __syncthreads();
    }

    // epilogue: add bias, store to g_P
    const int g = lane >> 2, t = lane & 3;
    #pragma unroll
    for (int mf = 0; mf < 4; mf++) {
        #pragma unroll
        for (int oct = 0; oct < 4; oct++) {
            const int col = n0 + wn + oct * 8 + 2 * t;
            const float b0 = __ldg(bias + col), b1 = __ldg(bias + col + 1);
            const int r0 = m0 + wm + mf * 16 + g;
            float2 v0 = { acc[mf][oct][0] + b0, acc[mf][oct][1] + b1 };
            float2 v1 = { acc[mf][oct][2] + b0, acc[mf][oct][3] + b1 };
            *(float2*)(g_P + (size_t)r0 * D_ + col)       = v0;
            *(float2*)(g_P + (size_t)(r0 + 8) * D_ + col) = v1;
        }
    }
}

// =============== compensated fp32 accumulation (TwoProd+TwoSum) ============
__device__ __forceinline__ void dot2_acc(float a, float b, float& s, float& c) {
    float p  = __fmul_rn(a, b);
    float e  = __fmaf_rn(a, b, -p);
    float t  = __fadd_rn(s, p);
    float bp = __fsub_rn(t, s);
    float e2 = __fadd_rn(__fsub_rn(s, __fsub_rn(t, bp)), __fsub_rn(p, bp));
    s = t;
    c = __fadd_rn(c, __fadd_rn(e, e2));
}

// ---------------- 2) row norms ---------------------------------------------
__global__ void rownorm_kernel() {
    const int r = blockIdx.x;
    const float* p = g_P + (size_t)r * D_;
    float s = 0.f, cc = 0.f;
    for (int k = threadIdx.x; k < D_; k += 256) {
        float v = p[k];
        dot2_acc(v, v, s, cc);
    }
    double d = (double)s + (double)cc;
    #pragma unroll
    for (int o = 16; o; o >>= 1) d += __shfl_down_sync(0xffffffffu, d, o);
    __shared__ double red[8];
    const int w = threadIdx.x >> 5, l = threadIdx.x & 31;
    if (l == 0) red[w] = d;
    __syncthreads();
    if (threadIdx.x == 0) {
        double tot = 0.0;
        #pragma unroll
        for (int i = 0; i < 8; i++) tot += red[i];
        double n = sqrt(tot);
        if (n < 1e-12) n = 1e-12;
        g_inv[r] = 1.0 / n;
    }
}

// ---------------- 3) attention + top-K (fused) -----------------------------
__global__ void attn_topk(const int* __restrict__ his_mask) {
    const int bc = blockIdx.x;      // candidate row
    const int b  = bc / C_;
    const int w  = threadIdx.x >> 5, l = threadIdx.x & 31;
    __shared__ double sc[64];
    const float* pc = g_P + (size_t)bc * D_;

    for (int h = w; h < H_; h += 8) {
        const int hrow = CROWS + b * H_ + h;
        const float* ph = g_P + (size_t)hrow * D_;
        float s = 0.f, cc = 0.f;
        for (int k = l; k < D_; k += 32)
            dot2_acc(pc[k], ph[k], s, cc);
        double d = (double)s + (double)cc;
        #pragma unroll
        for (int o = 16; o; o >>= 1) d += __shfl_down_sync(0xffffffffu, d, o);
        if (l == 0) {
            const bool valid = (his_mask[b * H_ + h] != 0) || (h < K_);
            sc[h] = valid ? d * g_inv[bc] * g_inv[hrow] : -CUDART_INF;
        }
    }
    if (threadIdx.x >= H_ && threadIdx.x < 64) sc[threadIdx.x] = -CUDART_INF;
    __syncthreads();

    if (threadIdx.x < 32) {
        double v0 = sc[l];
        double v1 = sc[l + 32];
        bool used0 = false, used1 = false;
        for (int k = 0; k < K_; k++) {
            double bv = -CUDART_INF;
            int    bi = 1 << 30;
            if (!used1)                        { bv = v1; bi = l + 32; }
            if (!used0 && (used1 || v0 >= v1)) { bv = v0; bi = l; }
            #pragma unroll
            for (int o = 16; o; o >>= 1) {
                double ov = __shfl_down_sync(0xffffffffu, bv, o);
                int    oi = __shfl_down_sync(0xffffffffu, bi, o);
                if (ov > bv || (ov == bv && oi < bi)) { bv = ov; bi = oi; }
            }
            bi = __shfl_sync(0xffffffffu, bi, 0);
            if (l == 0) g_idx[bc * K_ + k] = bi;
            if (bi == l)      used0 = true;
            if (bi == l + 32) used1 = true;
        }
    }
}

// ---------------- 5) embedding gather (bandwidth-bound) --------------------
__global__ void gather_emb(const float* __restrict__ emb, float* __restrict__ out) {
    const int sel  = blockIdx.x >> 3;
    const int part = blockIdx.x & 7;
    const int b    = sel / (C_ * K_);
    const int idx  = g_idx[sel];
    const float4* src = (const float4*)(emb + ((size_t)b * H_ + idx) * SE);
    float4*       dst = (float4*)(out + (size_t)sel * SE);
    const int base = part * 768;
    #pragma unroll
    for (int i = 0; i < 3; i++) {
        const int o = base + threadIdx.x + i * 256;
        dst[o] = src[o];
    }
}

// ---------------- 6) attention-mask gather ---------------------------------
__global__ void gather_mask(const int* __restrict__ am, float* __restrict__ outm) {
    const int i = blockIdx.x * blockDim.x + threadIdx.x;
    if (i >= SEL * S_) return;
    const int sel = i >> 5, s = i & 31;
    const int b   = sel / (C_ * K_);
    const int idx = g_idx[sel];
    outm[i] = (float)am[((size_t)b * H_ + idx) * S_ + s];
}

// ---------------------------------------------------------------------------
extern "C" void kernel_launch(void* const* d_in, const int* in_sizes, int n_in,
                              void* d_out, int out_size) {
    const float* cdd  = (const float*)d_in[0];   // [B,C,D]
    const float* his  = (const float*)d_in[1];   // [B,H,D]
    const float* emb  = (const float*)d_in[2];   // [B,H,S,E]
    const int*   am   = (const int*)  d_in[3];   // [B,H,S]
    const int*   hm   = (const int*)  d_in[4];   // [B,H,1]
    const float* W    = (const float*)d_in[5];   // [D,D]
    const float* bias = (const float*)d_in[6];   // [D]
    float* out = (float*)d_out;

    const size_t total = (size_t)ROWSP * D_ + (size_t)D_ * D_;
    split_kernel<<<(unsigned)((total + 255) / 256), 256>>>(cdd, his, W);
    gemm_mma<<<dim3(ROWSP / 128, D_ / 128), 256>>>(bias);
    rownorm_kernel<<<ROWS, 256>>>();
    attn_topk<<<CROWS, 256>>>(hm);
    gather_emb<<<SEL * 8, 256>>>(emb, out);
    gather_mask<<<(SEL * S_ + 255) / 256, 256>>>(am, out + (size_t)SEL * SE);
}

// round 5
// speedup vs baseline: 1.1694x; 1.0136x over previous
#include <cuda_runtime.h>
#include <cuda_bf16.h>
#include <math.h>
#include <math_constants.h>
#include <cstdint>

// Problem shapes (fixed by the dataset)
#define B_ 64
#define C_ 5
#define H_ 50
#define S_ 32
#define E_ 768
#define D_ 768
#define K_ 5
#define CROWS (B_*C_)            // 320 candidate rows
#define HROWS (B_*H_)            // 3200 history rows
#define ROWS (CROWS + HROWS)     // 3520 total projected rows
#define ROWSP 3584               // padded to multiple of 128
#define SEL (CROWS*K_)           // 1600 gather selections
#define SE (S_*E_)               // 24576 floats per selection

// ---------------- scratch (static device globals; no allocation) -----------
__device__ __nv_bfloat16 g_Xs[3][(size_t)ROWSP * D_];  // X split limbs (padded rows zeroed)
__device__ __nv_bfloat16 g_Ws[3][(size_t)D_ * D_];     // W split limbs
__device__ float  g_P[(size_t)ROWSP * D_];             // projected rows (padded)
__device__ int    g_idx[SEL];                          // top-K indices per (b,c)

// ======================= small helpers =====================================
__device__ __forceinline__ uint32_t smem_u32(const void* p) {
    uint32_t a;
    asm("{ .reg .u64 t; cvta.to.shared.u64 t, %1; cvt.u32.u64 %0, t; }" : "=r"(a) : "l"(p));
    return a;
}
__device__ __forceinline__ void cp_async16(uint32_t dst, const void* src) {
    asm volatile("cp.async.cg.shared.global [%0], [%1], 16;"
                 :: "r"(dst), "l"(__cvta_generic_to_global(src)));
}
#define CP_COMMIT() asm volatile("cp.async.commit_group;" ::: "memory")
#define CP_WAIT(n)  asm volatile("cp.async.wait_group %0;" :: "n"(n) : "memory")

__device__ __forceinline__ void ldsm4(uint32_t addr, uint32_t& r0, uint32_t& r1,
                                      uint32_t& r2, uint32_t& r3) {
    asm volatile("ldmatrix.sync.aligned.m8n8.x4.shared.b16 {%0,%1,%2,%3}, [%4];"
                 : "=r"(r0), "=r"(r1), "=r"(r2), "=r"(r3) : "r"(addr));
}
__device__ __forceinline__ void mma16816(float* c, const uint32_t* a,
                                         uint32_t b0, uint32_t b1) {
    asm volatile("mma.sync.aligned.m16n8k16.row.col.f32.bf16.bf16.f32 "
                 "{%0,%1,%2,%3}, {%4,%5,%6,%7}, {%8,%9}, {%0,%1,%2,%3};"
                 : "+f"(c[0]), "+f"(c[1]), "+f"(c[2]), "+f"(c[3])
                 : "r"(a[0]), "r"(a[1]), "r"(a[2]), "r"(a[3]), "r"(b0), "r"(b1));
}

__device__ __forceinline__ uint32_t pack_bf2(float lo, float hi) {
    __nv_bfloat162 t = __floats2bfloat162_rn(lo, hi);
    return *(uint32_t*)&t;
}
__device__ __forceinline__ float bf_trunc(float v, float& rem) {
    __nv_bfloat16 b = __float2bfloat16(v);
    float f = __bfloat162float(b);
    rem = v - f;
    return f;
}

// ================== 0) split fp32 -> 3 bf16 limbs (vectorized) =============
__global__ void split_kernel(const float* __restrict__ cdd,
                             const float* __restrict__ his,
                             const float* __restrict__ W) {
    const size_t NX4 = (size_t)ROWSP * D_ / 4;
    const size_t NW4 = (size_t)D_ * D_ / 4;
    size_t i = (size_t)blockIdx.x * blockDim.x + threadIdx.x;
    float4 v;
    size_t base;
    if (i < NX4) {
        base = i * 4;
        size_t row = base / D_;
        if (row < CROWS)      v = *(const float4*)(cdd + base);
        else if (row < ROWS)  v = *(const float4*)(his + (base - (size_t)CROWS * D_));
        else                  v = make_float4(0.f, 0.f, 0.f, 0.f);
    } else if (i < NX4 + NW4) {
        base = (i - NX4) * 4;
        v = *(const float4*)(W + base);
    } else return;

    float f[4] = {v.x, v.y, v.z, v.w};
    uint32_t limb[3][2];
    #pragma unroll
    for (int lb = 0; lb < 3; lb++) {
        float t[4];
        #pragma unroll
        for (int j = 0; j < 4; j++) { float r; t[j] = bf_trunc(f[j], r); f[j] = r; }
        limb[lb][0] = pack_bf2(t[0], t[1]);
        limb[lb][1] = pack_bf2(t[2], t[3]);
    }
    if (i < NX4) {
        #pragma unroll
        for (int lb = 0; lb < 3; lb++) *(uint2*)&g_Xs[lb][base] = make_uint2(limb[lb][0], limb[lb][1]);
    } else {
        #pragma unroll
        for (int lb = 0; lb < 3; lb++) *(uint2*)&g_Ws[lb][base] = make_uint2(limb[lb][0], limb[lb][1]);
    }
}

// ================== 1) mma.sync bf16x3 GEMM: P = X·Wᵀ + b ==================
#define NPROD 6
#define KC 32
#define NKT (D_ / KC)                    // 24
#define NIT (NPROD * NKT)                // 144
#define SSTRIDE 40                       // bf16 elements per smem row

__constant__ int c_pa[NPROD] = {0, 0, 1, 0, 2, 1};
__constant__ int c_pb[NPROD] = {0, 1, 0, 2, 0, 1};

__global__ void __launch_bounds__(256, 2)
gemm_mma(const float* __restrict__ bias) {
    __shared__ __nv_bfloat16 sA[2][128 * SSTRIDE];
    __shared__ __nv_bfloat16 sB[2][128 * SSTRIDE];

    const int tid  = threadIdx.x;
    const int wid  = tid >> 5, lane = tid & 31;
    const int m0   = blockIdx.x * 128;
    const int n0   = blockIdx.y * 128;
    const int wm   = (wid >> 2) * 64;
    const int wn   = (wid & 3) * 32;

    const uint32_t sAb[2] = { smem_u32(&sA[0][0]), smem_u32(&sA[1][0]) };
    const uint32_t sBb[2] = { smem_u32(&sB[0][0]), smem_u32(&sB[1][0]) };

    const int jrow[2] = { tid >> 2, (tid + 256) >> 2 };
    const int jq  = tid & 3;

    float acc[4][4][4];
    #pragma unroll
    for (int i = 0; i < 4; i++)
        #pragma unroll
        for (int j = 0; j < 4; j++)
            #pragma unroll
            for (int v = 0; v < 4; v++) acc[i][j][v] = 0.f;

    auto load_tile = [&](int it, int buf) {
        const int p  = it / NKT;
        const int kb = (it % NKT) * KC;
        const __nv_bfloat16* Asrc = g_Xs[c_pa[p]];
        const __nv_bfloat16* Bsrc = g_Ws[c_pb[p]];
        #pragma unroll
        for (int h = 0; h < 2; h++) {
            const int row = jrow[h];
            cp_async16(sAb[buf] + (uint32_t)(row * SSTRIDE + jq * 8) * 2,
                       Asrc + (size_t)(m0 + row) * D_ + kb + jq * 8);
            cp_async16(sBb[buf] + (uint32_t)(row * SSTRIDE + jq * 8) * 2,
                       Bsrc + (size_t)(n0 + row) * D_ + kb + jq * 8);
        }
        CP_COMMIT();
    };

    load_tile(0, 0);

    const int lrow = lane & 15;
    const int lcol = (lane >> 4) << 3;

    for (int it = 0; it < NIT; it++) {
        const int buf = it & 1;
        if (it + 1 < NIT) { load_tile(it + 1, buf ^ 1); CP_WAIT(1); }
        else              { CP_WAIT(0); }
        __syncthreads();

        #pragma unroll
        for (int kh = 0; kh < 2; kh++) {
            const int kb = kh * 16;
            uint32_t a[4][4];
            #pragma unroll
            for (int mf = 0; mf < 4; mf++) {
                uint32_t addr = sAb[buf] +
                    (uint32_t)((wm + mf * 16 + lrow) * SSTRIDE + kb + lcol) * 2;
                ldsm4(addr, a[mf][0], a[mf][1], a[mf][2], a[mf][3]);
            }
            uint32_t bfr[2][4];
            #pragma unroll
            for (int nb = 0; nb < 2; nb++) {
                uint32_t addr = sBb[buf] +
                    (uint32_t)((wn + nb * 16 + lrow) * SSTRIDE + kb + lcol) * 2;
                ldsm4(addr, bfr[nb][0], bfr[nb][1], bfr[nb][2], bfr[nb][3]);
            }
            #pragma unroll
            for (int mf = 0; mf < 4; mf++)
                #pragma unroll
                for (int oct = 0; oct < 4; oct++) {
                    const int nb = oct >> 1, par = oct & 1;
                    mma16816(acc[mf][oct], a[mf], bfr[nb][par], bfr[nb][par + 2]);
                }
        }
        __syncthreads();
    }

    const int g = lane >> 2, t = lane & 3;
    #pragma unroll
    for (int mf = 0; mf < 4; mf++) {
        #pragma unroll
        for (int oct = 0; oct < 4; oct++) {
            const int col = n0 + wn + oct * 8 + 2 * t;
            const float b0 = __ldg(bias + col), b1 = __ldg(bias + col + 1);
            const int r0 = m0 + wm + mf * 16 + g;
            float2 v0 = { acc[mf][oct][0] + b0, acc[mf][oct][1] + b1 };
            float2 v1 = { acc[mf][oct][2] + b0, acc[mf][oct][3] + b1 };
            *(float2*)(g_P + (size_t)r0 * D_ + col)       = v0;
            *(float2*)(g_P + (size_t)(r0 + 8) * D_ + col) = v1;
        }
    }
}

// =============== compensated fp32 accumulation (TwoProd+TwoSum) ============
__device__ __forceinline__ void dot2_acc(float a, float b, float& s, float& c) {
    float p  = __fmul_rn(a, b);
    float e  = __fmaf_rn(a, b, -p);
    float t  = __fadd_rn(s, p);
    float bp = __fsub_rn(t, s);
    float e2 = __fadd_rn(__fsub_rn(s, __fsub_rn(t, bp)), __fsub_rn(p, bp));
    s = t;
    c = __fadd_rn(c, __fadd_rn(e, e2));
}

// ---------- 2+3+4) fused norms + attention + top-K, one block per batch ----
__global__ void __launch_bounds__(256, 4)
attn_topk(const int* __restrict__ his_mask) {
    const int b = blockIdx.x;
    const int tid = threadIdx.x;
    const int w = tid >> 5, l = tid & 31;

    __shared__ float  cand[C_][D_];      // 15 KB
    __shared__ double invc[C_];
    __shared__ double sc[C_][64];        // scores, padded to 64

    // load 5 candidate rows into smem
    for (int i = tid; i < C_ * (D_ / 4); i += 256) {
        const int c = i / (D_ / 4), j = i % (D_ / 4);
        ((float4*)cand[c])[j] = ((const float4*)(g_P + (size_t)(b * C_ + c) * D_))[j];
    }
    for (int i = tid; i < C_ * 64; i += 256) ((double*)sc)[i] = -CUDART_INF;
    __syncthreads();

    // candidate norms (warps 0..4)
    if (w < C_) {
        float s = 0.f, cc = 0.f;
        for (int k = l; k < D_; k += 32) { float v = cand[w][k]; dot2_acc(v, v, s, cc); }
        double d = (double)s + (double)cc;
        #pragma unroll
        for (int o = 16; o; o >>= 1) d += __shfl_down_sync(0xffffffffu, d, o);
        if (l == 0) invc[w] = 1.0 / fmax(sqrt(d), 1e-12);
    }
    __syncthreads();

    // stream history rows: 5 candidate dots + own norm, 6 independent chains
    for (int h = w; h < H_; h += 8) {
        const float4* ph = (const float4*)(g_P + (size_t)(CROWS + b * H_ + h) * D_);
        float s[C_] = {}, cc[C_] = {};
        float sn = 0.f, cn = 0.f;
        #pragma unroll
        for (int j = 0; j < D_ / 128; j++) {        // 6 float4s per lane
            const int idx = l + 32 * j;
            const float4 v = ph[idx];
            dot2_acc(v.x, v.x, sn, cn); dot2_acc(v.y, v.y, sn, cn);
            dot2_acc(v.z, v.z, sn, cn); dot2_acc(v.w, v.w, sn, cn);
            #pragma unroll
            for (int c = 0; c < C_; c++) {
                const float4 cv = ((const float4*)cand[c])[idx];
                dot2_acc(v.x, cv.x, s[c], cc[c]); dot2_acc(v.y, cv.y, s[c], cc[c]);
                dot2_acc(v.z, cv.z, s[c], cc[c]); dot2_acc(v.w, cv.w, s[c], cc[c]);
            }
        }
        double dn = (double)sn + (double)cn;
        double dc[C_];
        #pragma unroll
        for (int c = 0; c < C_; c++) dc[c] = (double)s[c] + (double)cc[c];
        #pragma unroll
        for (int o = 16; o; o >>= 1) {
            dn += __shfl_down_sync(0xffffffffu, dn, o);
            #pragma unroll
            for (int c = 0; c < C_; c++) dc[c] += __shfl_down_sync(0xffffffffu, dc[c], o);
        }
        if (l == 0) {
            const bool valid = (his_mask[b * H_ + h] != 0) || (h < K_);
            const double invh = 1.0 / fmax(sqrt(dn), 1e-12);
            #pragma unroll
            for (int c = 0; c < C_; c++)
                sc[c][h] = valid ? dc[c] * invc[c] * invh : -CUDART_INF;
        }
    }
    __syncthreads();

    // top-K: warp c handles candidate c
    if (w < C_) {
        double v0 = sc[w][l];
        double v1 = sc[w][l + 32];
        bool used0 = false, used1 = false;
        for (int k = 0; k < K_; k++) {
            double bv = -CUDART_INF;
            int    bi = 1 << 30;
            if (!used1)                        { bv = v1; bi = l + 32; }
            if (!used0 && (used1 || v0 >= v1)) { bv = v0; bi = l; }
            #pragma unroll
            for (int o = 16; o; o >>= 1) {
                double ov = __shfl_down_sync(0xffffffffu, bv, o);
                int    oi = __shfl_down_sync(0xffffffffu, bi, o);
                if (ov > bv || (ov == bv && oi < bi)) { bv = ov; bi = oi; }
            }
            bi = __shfl_sync(0xffffffffu, bi, 0);
            if (l == 0) g_idx[(b * C_ + w) * K_ + k] = bi;
            if (bi == l)      used0 = true;
            if (bi == l + 32) used1 = true;
        }
    }
}

// ---------------- 5) embedding gather (bandwidth-bound) --------------------
__global__ void gather_emb(const float* __restrict__ emb, float* __restrict__ out) {
    const int sel  = blockIdx.x >> 3;
    const int part = blockIdx.x & 7;
    const int b    = sel / (C_ * K_);
    const int idx  = g_idx[sel];
    const float4* src = (const float4*)(emb + ((size_t)b * H_ + idx) * SE);
    float4*       dst = (float4*)(out + (size_t)sel * SE);
    const int base = part * 768;
    #pragma unroll
    for (int i = 0; i < 3; i++) {
        const int o = base + threadIdx.x + i * 256;
        dst[o] = src[o];
    }
}

// ---------------- 6) attention-mask gather ---------------------------------
__global__ void gather_mask(const int* __restrict__ am, float* __restrict__ outm) {
    const int i = blockIdx.x * blockDim.x + threadIdx.x;
    if (i >= SEL * S_) return;
    const int sel = i >> 5, s = i & 31;
    const int b   = sel / (C_ * K_);
    const int idx = g_idx[sel];
    outm[i] = (float)am[((size_t)b * H_ + idx) * S_ + s];
}

// ---------------------------------------------------------------------------
extern "C" void kernel_launch(void* const* d_in, const int* in_sizes, int n_in,
                              void* d_out, int out_size) {
    const float* cdd  = (const float*)d_in[0];   // [B,C,D]
    const float* his  = (const float*)d_in[1];   // [B,H,D]
    const float* emb  = (const float*)d_in[2];   // [B,H,S,E]
    const int*   am   = (const int*)  d_in[3];   // [B,H,S]
    const int*   hm   = (const int*)  d_in[4];   // [B,H,1]
    const float* W    = (const float*)d_in[5];   // [D,D]
    const float* bias = (const float*)d_in[6];   // [D]
    float* out = (float*)d_out;

    const size_t total4 = ((size_t)ROWSP * D_ + (size_t)D_ * D_) / 4;
    split_kernel<<<(unsigned)((total4 + 255) / 256), 256>>>(cdd, his, W);
    gemm_mma<<<dim3(ROWSP / 128, D_ / 128), 256>>>(bias);
    attn_topk<<<B_, 256>>>(hm);
    gather_emb<<<SEL * 8, 256>>>(emb, out);
    gather_mask<<<(SEL * S_ + 255) / 256, 256>>>(am, out + (size_t)SEL * SE);
}